// round 9
// baseline (speedup 1.0000x reference)
#include <cuda_runtime.h>
#include <cuda_bf16.h>
#include <cstdint>

#define BN 8
#define TN 2048
#define CN 1024
#define HN 128

// bf16 split scratch (allocation-free rule: __device__ globals)
__device__ __align__(16) __nv_bfloat16 g_kh[BN * TN * HN];   // k hi [b*T+t][h]  (q == k)
__device__ __align__(16) __nv_bfloat16 g_kl[BN * TN * HN];   // k lo
__device__ __align__(16) __nv_bfloat16 g_vh[BN * HN * TN];   // v^T hi [b][h][t]
__device__ __align__(16) __nv_bfloat16 g_vl[BN * HN * TN];   // v^T lo
// pre-split inputs
__device__ __align__(16) __nv_bfloat16 g_xh[BN * TN * CN];
__device__ __align__(16) __nv_bfloat16 g_xl[BN * TN * CN];
__device__ __align__(16) __nv_bfloat16 g_wkh[HN * CN];
__device__ __align__(16) __nv_bfloat16 g_wkl[HN * CN];
__device__ __align__(16) __nv_bfloat16 g_wvh[HN * CN];
__device__ __align__(16) __nv_bfloat16 g_wvl[HN * CN];

// ---------------------------------------------------------------------------
__device__ __forceinline__ uint32_t smem_u32(const void* p) {
    uint32_t a;
    asm("{ .reg .u64 t; cvta.to.shared.u64 t, %1; cvt.u32.u64 %0, t; }" : "=r"(a) : "l"(p));
    return a;
}
__device__ __forceinline__ float fex2(float x) {
    float r; asm("ex2.approx.f32 %0, %1;" : "=f"(r) : "f"(x)); return r;
}
__device__ __forceinline__ void mma_bf16(float* d, const uint32_t* a, const uint32_t* b) {
    asm volatile("mma.sync.aligned.m16n8k16.row.col.f32.bf16.bf16.f32 "
        "{%0,%1,%2,%3}, {%4,%5,%6,%7}, {%8,%9}, {%0,%1,%2,%3};"
        : "+f"(d[0]), "+f"(d[1]), "+f"(d[2]), "+f"(d[3])
        : "r"(a[0]), "r"(a[1]), "r"(a[2]), "r"(a[3]), "r"(b[0]), "r"(b[1]));
}
__device__ __forceinline__ void ldmx4(uint32_t* r, uint32_t a) {
    asm volatile("ldmatrix.sync.aligned.m8n8.x4.shared.b16 {%0,%1,%2,%3}, [%4];"
        : "=r"(r[0]), "=r"(r[1]), "=r"(r[2]), "=r"(r[3]) : "r"(a));
}
__device__ __forceinline__ void cpa16(uint32_t d, const void* s) {
    asm volatile("cp.async.cg.shared.global [%0], [%1], 16;" :: "r"(d), "l"(s));
}
#define CP_COMMIT() asm volatile("cp.async.commit_group;" ::: "memory")
#define CP_WAIT0()  asm volatile("cp.async.wait_group 0;" ::: "memory")

__device__ __forceinline__ uint32_t aAddr(int r0, int kbyte, int stride, int lane) {
    int row = r0 + (lane & 7) + (lane & 8);
    int bo  = kbyte + ((lane >> 4) << 4);
    return (uint32_t)(row * stride + bo);
}
__device__ __forceinline__ uint32_t bAddr(int n0, int kbyte, int stride, int lane) {
    int row = n0 + (lane & 7) + ((lane & 16) >> 1);
    int bo  = kbyte + ((lane & 8) << 1);
    return (uint32_t)(row * stride + bo);
}
__device__ __forceinline__ void spl(float a, float b, uint32_t& H, uint32_t& L) {
    __nv_bfloat162 h = __floats2bfloat162_rn(a, b);
    H = *reinterpret_cast<uint32_t*>(&h);
    float ra = a - __bfloat162float(__low2bfloat16(h));
    float rb = b - __bfloat162float(__high2bfloat16(h));
    __nv_bfloat162 l = __floats2bfloat162_rn(ra, rb);
    L = *reinterpret_cast<uint32_t*>(&l);
}

// ---------------------------------------------------------------------------
// Pre-split: fp32 -> bf16 hi/lo for x, Wk, Wv. Streaming, float4 per thread.
// ---------------------------------------------------------------------------
#define N4X (BN * TN * CN / 4)     // 4194304
#define N4W (HN * CN / 4)          // 32768

__global__ __launch_bounds__(256) void split_kernel(
    const float* __restrict__ x,
    const float* __restrict__ Wk,
    const float* __restrict__ Wv)
{
    const int i = blockIdx.x * 256 + threadIdx.x;
    const float* src; __nv_bfloat16 *dh, *dl; int j;
    if (i < N4X)                { src = x;  dh = g_xh;  dl = g_xl;  j = i; }
    else if (i < N4X + N4W)     { src = Wk; dh = g_wkh; dl = g_wkl; j = i - N4X; }
    else                        { src = Wv; dh = g_wvh; dl = g_wvl; j = i - N4X - N4W; }
    float4 f = *(const float4*)(src + (size_t)j * 4);
    uint32_t h0, l0, h1, l1;
    spl(f.x, f.y, h0, l0); spl(f.z, f.w, h1, l1);
    *(uint2*)(dh + (size_t)j * 4) = make_uint2(h0, h1);
    *(uint2*)(dl + (size_t)j * 4) = make_uint2(l0, l1);
}

// ---------------------------------------------------------------------------
// Projection: cp.async double-buffered bf16 tiles, BK=32, 3-pass split mma.
// Stage layout (stride 80 rows): XH +0, XL +10240, WH +20480, WL +30720.
// ---------------------------------------------------------------------------
#define P_STAGE 40960
#define P_SMEM  81920     // 2 stages; v staging (67584 B) overlays stage 0

__device__ __forceinline__ void proj_prefetch(
    uint32_t sb, int stage, const __nv_bfloat16* wh, const __nv_bfloat16* wl,
    int t0, int c0, int tid)
{
    const int row = tid >> 1;
    const uint32_t base = sb + stage * P_STAGE + row * 80;
    if (tid & 1) {
        const __nv_bfloat16* sh = wh + (size_t)row * CN + c0;
        const __nv_bfloat16* sl = wl + (size_t)row * CN + c0;
#pragma unroll
        for (int i = 0; i < 4; ++i) cpa16(base + 20480 + i * 16, sh + i * 8);
#pragma unroll
        for (int i = 0; i < 4; ++i) cpa16(base + 30720 + i * 16, sl + i * 8);
    } else {
        const __nv_bfloat16* sh = g_xh + (size_t)(t0 + row) * CN + c0;
        const __nv_bfloat16* sl = g_xl + (size_t)(t0 + row) * CN + c0;
#pragma unroll
        for (int i = 0; i < 4; ++i) cpa16(base + i * 16, sh + i * 8);
#pragma unroll
        for (int i = 0; i < 4; ++i) cpa16(base + 10240 + i * 16, sl + i * 8);
    }
}

__global__ __launch_bounds__(256, 2) void proj_kernel()
{
    extern __shared__ char smc[];
    const uint32_t sb = smem_u32(smc);
    const int tid = threadIdx.x;
    const int lane = tid & 31, warp = tid >> 5;
    const int t0 = blockIdx.x * 128;
    const int mode = blockIdx.y;
    const __nv_bfloat16* wh = mode ? g_wvh : g_wkh;
    const __nv_bfloat16* wl = mode ? g_wvl : g_wkl;

    const int m0 = (warp >> 1) * 32;
    const int n0 = (warp & 1) * 64;

    float acc[2][8][4];
#pragma unroll
    for (int i = 0; i < 2; ++i)
#pragma unroll
        for (int j = 0; j < 8; ++j)
#pragma unroll
            for (int q = 0; q < 4; ++q) acc[i][j][q] = 0.f;

    proj_prefetch(sb, 0, wh, wl, t0, 0, tid);
    CP_COMMIT();

    for (int it = 0; it < 32; ++it) {
        CP_WAIT0();
        __syncthreads();
        if (it + 1 < 32) { proj_prefetch(sb, (it + 1) & 1, wh, wl, t0, (it + 1) * 32, tid); CP_COMMIT(); }
        const uint32_t stb = sb + (it & 1) * P_STAGE;
#pragma unroll
        for (int kk = 0; kk < 2; ++kk) {
            const int kb = kk * 32;
            uint32_t ah[2][4], al[2][4];
            ldmx4(ah[0], stb + aAddr(m0,      kb, 80, lane));
            ldmx4(ah[1], stb + aAddr(m0 + 16, kb, 80, lane));
            ldmx4(al[0], stb + 10240 + aAddr(m0,      kb, 80, lane));
            ldmx4(al[1], stb + 10240 + aAddr(m0 + 16, kb, 80, lane));
#pragma unroll
            for (int np = 0; np < 4; ++np) {
                uint32_t bh[4], bl[4];
                ldmx4(bh, stb + 20480 + bAddr(n0 + np * 16, kb, 80, lane));
                ldmx4(bl, stb + 30720 + bAddr(n0 + np * 16, kb, 80, lane));
#pragma unroll
                for (int mi = 0; mi < 2; ++mi) {
                    mma_bf16(acc[mi][np * 2],     ah[mi], bh);
                    mma_bf16(acc[mi][np * 2],     ah[mi], bl);
                    mma_bf16(acc[mi][np * 2],     al[mi], bh);
                    mma_bf16(acc[mi][np * 2 + 1], ah[mi], bh + 2);
                    mma_bf16(acc[mi][np * 2 + 1], ah[mi], bl + 2);
                    mma_bf16(acc[mi][np * 2 + 1], al[mi], bh + 2);
                }
            }
        }
    }
    __syncthreads();   // all compute done before staging overlays stage 0

    if (mode == 0) {
#pragma unroll
        for (int mi = 0; mi < 2; ++mi)
#pragma unroll
            for (int ni = 0; ni < 8; ++ni) {
                int gr  = t0 + m0 + mi * 16 + (lane >> 2);
                int col = n0 + ni * 8 + (lane & 3) * 2;
                uint32_t H, L;
                spl(acc[mi][ni][0], acc[mi][ni][1], H, L);
                *(uint32_t*)(g_kh + (size_t)gr * HN + col) = H;
                *(uint32_t*)(g_kl + (size_t)gr * HN + col) = L;
                spl(acc[mi][ni][2], acc[mi][ni][3], H, L);
                *(uint32_t*)(g_kh + (size_t)(gr + 8) * HN + col) = H;
                *(uint32_t*)(g_kl + (size_t)(gr + 8) * HN + col) = L;
            }
    } else {
        float* stg = (float*)smc;   // overlay stage 0/1 (128*132*4 = 67584 <= 81920)
#pragma unroll
        for (int mi = 0; mi < 2; ++mi)
#pragma unroll
            for (int ni = 0; ni < 8; ++ni) {
                int r = m0 + mi * 16 + (lane >> 2);
                int c = n0 + ni * 8 + (lane & 3) * 2;
                *(float2*)&stg[r * 132 + c]       = make_float2(acc[mi][ni][0], acc[mi][ni][1]);
                *(float2*)&stg[(r + 8) * 132 + c] = make_float2(acc[mi][ni][2], acc[mi][ni][3]);
            }
        __syncthreads();
        const int h = tid >> 1, th = (tid & 1) * 64;
        const int bb = t0 >> 11, tt0 = t0 & (TN - 1);
        __nv_bfloat16* dh = g_vh + ((size_t)bb * HN + h) * TN + tt0 + th;
        __nv_bfloat16* dl = g_vl + ((size_t)bb * HN + h) * TN + tt0 + th;
#pragma unroll
        for (int g = 0; g < 8; ++g) {
            uint32_t H[4], L[4];
#pragma unroll
            for (int j = 0; j < 4; ++j) {
                float a = stg[(th + g * 8 + j * 2) * 132 + h];
                float b = stg[(th + g * 8 + j * 2 + 1) * 132 + h];
                spl(a, b, H[j], L[j]);
            }
            *(uint4*)(dh + g * 8) = make_uint4(H[0], H[1], H[2], H[3]);
            *(uint4*)(dl + g * 8) = make_uint4(L[0], L[1], L[2], L[3]);
        }
    }
}

// ---------------------------------------------------------------------------
// Attention: balanced pairing (33 iters/block), cp.async double-buffered K/V.
// ---------------------------------------------------------------------------
#define AQ_H 0
#define AQ_L 17408
#define AK0  34816          // K stage s: +s*34816 (hi +0, lo +17408)
#define AV0  104448         // V stage s: +s*36864 (hi +0, lo +18432)
#define A_SMEM 178176
#define AP_O  34816         // epilogue partials overlay K stages
#define AP_L  100352

__device__ __forceinline__ void attn_prefetch_q(uint32_t sb, int b, int q0, int tid) {
    const int row = tid >> 2, qb = tid & 3;
    const __nv_bfloat16* sh = g_kh + (size_t)(b * TN + q0 + row) * HN + qb * 32;
    const __nv_bfloat16* sl = g_kl + (size_t)(b * TN + q0 + row) * HN + qb * 32;
    const uint32_t base = sb + row * 272 + qb * 64;
#pragma unroll
    for (int i = 0; i < 4; ++i) cpa16(base + AQ_H + i * 16, sh + i * 8);
#pragma unroll
    for (int i = 0; i < 4; ++i) cpa16(base + AQ_L + i * 16, sl + i * 8);
}
__device__ __forceinline__ void attn_prefetch_kv(uint32_t sb, int stage, int b, int k0, int tid) {
    const uint32_t kb_ = sb + AK0 + stage * 34816;
    const int row = tid >> 2, qb = tid & 3;
    const __nv_bfloat16* sh = g_kh + (size_t)(b * TN + k0 + row) * HN + qb * 32;
    const __nv_bfloat16* sl = g_kl + (size_t)(b * TN + k0 + row) * HN + qb * 32;
#pragma unroll
    for (int i = 0; i < 4; ++i) cpa16(kb_ + row * 272 + qb * 64 + i * 16, sh + i * 8);
#pragma unroll
    for (int i = 0; i < 4; ++i) cpa16(kb_ + 17408 + row * 272 + qb * 64 + i * 16, sl + i * 8);
    const uint32_t vb_ = sb + AV0 + stage * 36864;
    const int vrow = tid >> 1, v2 = tid & 1;
    const __nv_bfloat16* svh = g_vh + ((size_t)b * HN + vrow) * TN + k0 + v2 * 32;
    const __nv_bfloat16* svl = g_vl + ((size_t)b * HN + vrow) * TN + k0 + v2 * 32;
#pragma unroll
    for (int i = 0; i < 4; ++i) cpa16(vb_ + vrow * 144 + v2 * 64 + i * 16, svh + i * 8);
#pragma unroll
    for (int i = 0; i < 4; ++i) cpa16(vb_ + 18432 + vrow * 144 + v2 * 64 + i * 16, svl + i * 8);
}

__global__ __launch_bounds__(256, 1) void attn_kernel(float* __restrict__ out)
{
    extern __shared__ char smc[];
    const uint32_t sb = smem_u32(smc);
    const int tid = threadIdx.x;
    const int lane = tid & 31, warp = tid >> 5;
    const int wm = warp & 3;          // row group: q-rows 16*wm .. +15
    const int wk = warp >> 2;         // key half: keys 32*wk .. +31
    const int bx = blockIdx.x, b = blockIdx.y;
    const float SC = 1.4426950408889634f / 32.0f;   // log2(e) * C^-0.5

#pragma unroll 1
    for (int ph = 0; ph < 2; ++ph) {
        const int qt = ph ? bx : (31 - bx);
        const int q0 = qt * 64;
        const int nkt = qt + 1;

        attn_prefetch_q(sb, b, q0, tid);
        attn_prefetch_kv(sb, 0, b, 0, tid);
        CP_COMMIT();

        uint32_t qfh[8][4], qfl[8][4];
        float o[16][4];
#pragma unroll
        for (int i = 0; i < 16; ++i)
#pragma unroll
            for (int j = 0; j < 4; ++j) o[i][j] = 0.f;
        float ls0 = 0.f, ls1 = 0.f;
        const int qr0 = q0 + wm * 16 + (lane >> 2);
        const int qr1 = qr0 + 8;

        for (int kt = 0; kt < nkt; ++kt) {
            const int cur = kt & 1;
            CP_WAIT0();
            __syncthreads();
            if (kt == 0) {
#pragma unroll
                for (int kk = 0; kk < 8; ++kk) {
                    ldmx4(qfh[kk], sb + AQ_H + aAddr(wm * 16, kk * 32, 272, lane));
                    ldmx4(qfl[kk], sb + AQ_L + aAddr(wm * 16, kk * 32, 272, lane));
                }
            }
            if (kt + 1 < nkt) { attn_prefetch_kv(sb, 1 - cur, b, (kt + 1) * 64, tid); CP_COMMIT(); }

            const uint32_t kh_ = sb + AK0 + cur * 34816;
            const uint32_t kl_ = kh_ + 17408;
            const uint32_t vh_ = sb + AV0 + cur * 36864;
            const uint32_t vl_ = vh_ + 18432;
            const int k0 = kt * 64;

            // ---- S = Q.K^T : warp = 16 rows x 32 keys, 3-pass split ----
            float s[4][4];
#pragma unroll
            for (int i = 0; i < 4; ++i)
#pragma unroll
                for (int j = 0; j < 4; ++j) s[i][j] = 0.f;
#pragma unroll
            for (int kk = 0; kk < 8; ++kk) {
                const int kb = kk * 32;
#pragma unroll
                for (int np = 0; np < 2; ++np) {
                    uint32_t bh[4], bl[4];
                    ldmx4(bh, kh_ + bAddr(wk * 32 + np * 16, kb, 272, lane));
                    ldmx4(bl, kl_ + bAddr(wk * 32 + np * 16, kb, 272, lane));
                    mma_bf16(s[np * 2],     qfh[kk], bh);
                    mma_bf16(s[np * 2],     qfh[kk], bl);
                    mma_bf16(s[np * 2],     qfl[kk], bh);
                    mma_bf16(s[np * 2 + 1], qfh[kk], bh + 2);
                    mma_bf16(s[np * 2 + 1], qfh[kk], bl + 2);
                    mma_bf16(s[np * 2 + 1], qfl[kk], bh + 2);
                }
            }

            // ---- softmax (no max; bounded logits) + P frags ----
            uint32_t pH[2][4], pL[2][4];
#pragma unroll
            for (int j = 0; j < 4; ++j) {
                const int colb = k0 + wk * 32 + j * 8 + (lane & 3) * 2;
                float e0 = (colb     <= qr0) ? fex2(s[j][0] * SC) : 0.f;
                float e1 = (colb + 1 <= qr0) ? fex2(s[j][1] * SC) : 0.f;
                float e2 = (colb     <= qr1) ? fex2(s[j][2] * SC) : 0.f;
                float e3 = (colb + 1 <= qr1) ? fex2(s[j][3] * SC) : 0.f;
                ls0 += e0 + e1; ls1 += e2 + e3;
                const int kkf = j >> 1, hf = (j & 1) * 2;
                spl(e0, e1, pH[kkf][hf + 0], pL[kkf][hf + 0]);
                spl(e2, e3, pH[kkf][hf + 1], pL[kkf][hf + 1]);
            }

            // ---- O += P.V : 16 rows x 128 h, k-dim = warp's 32 keys ----
#pragma unroll
            for (int kkf = 0; kkf < 2; ++kkf) {
                const int kb = (wk * 32 + kkf * 16) * 2;
#pragma unroll
                for (int np = 0; np < 8; ++np) {
                    uint32_t vh[4], vl[4];
                    ldmx4(vh, vh_ + bAddr(np * 16, kb, 144, lane));
                    ldmx4(vl, vl_ + bAddr(np * 16, kb, 144, lane));
                    mma_bf16(o[np * 2],     pH[kkf], vh);
                    mma_bf16(o[np * 2],     pH[kkf], vl);
                    mma_bf16(o[np * 2],     pL[kkf], vh);
                    mma_bf16(o[np * 2 + 1], pH[kkf], vh + 2);
                    mma_bf16(o[np * 2 + 1], pH[kkf], vl + 2);
                    mma_bf16(o[np * 2 + 1], pL[kkf], vh + 2);
                }
            }
        }

        // ---- combine key-halves through smem, normalize, store ----
        ls0 += __shfl_xor_sync(0xffffffffu, ls0, 1);
        ls0 += __shfl_xor_sync(0xffffffffu, ls0, 2);
        ls1 += __shfl_xor_sync(0xffffffffu, ls1, 1);
        ls1 += __shfl_xor_sync(0xffffffffu, ls1, 2);

        __syncthreads();   // all compute + cp.async drained; reuse K region
        {
            float* pO = (float*)(smc + AP_O) + wk * 64 * 128;
            float* pl = (float*)(smc + AP_L) + wk * 64;
            const int r0 = wm * 16 + (lane >> 2), r1 = r0 + 8;
#pragma unroll
            for (int ni = 0; ni < 16; ++ni) {
                const int col = ni * 8 + (lane & 3) * 2;
                *(float2*)&pO[r0 * 128 + col] = make_float2(o[ni][0], o[ni][1]);
                *(float2*)&pO[r1 * 128 + col] = make_float2(o[ni][2], o[ni][3]);
            }
            if ((lane & 3) == 0) { pl[r0] = ls0; pl[r1] = ls1; }
        }
        __syncthreads();
        {
            const float* p0 = (const float*)(smc + AP_O);
            const float* p1 = p0 + 64 * 128;
            const float* pl = (const float*)(smc + AP_L);
            const int row = tid >> 2, cb = (tid & 3) * 32;
            const float inv = 1.0f / (pl[row] + pl[64 + row]);
            float* orow = out + (size_t)(b * TN + q0 + row) * HN + cb;
#pragma unroll
            for (int j = 0; j < 8; ++j) {
                float4 a = *(const float4*)&p0[row * 128 + cb + j * 4];
                float4 c = *(const float4*)&p1[row * 128 + cb + j * 4];
                *(float4*)(orow + j * 4) = make_float4((a.x + c.x) * inv, (a.y + c.y) * inv,
                                                       (a.z + c.z) * inv, (a.w + c.w) * inv);
            }
        }
        __syncthreads();   // partial reads done before next phase's prefetch overwrites
    }
}

// ---------------------------------------------------------------------------
extern "C" void kernel_launch(void* const* d_in, const int* in_sizes, int n_in,
                              void* d_out, int out_size)
{
    const float* x  = (const float*)d_in[0];
    const float* Wk = (const float*)d_in[1];
    // d_in[2] = Wq — unused: reference computes q with Wk (source bug, kept faithfully)
    const float* Wv = (const float*)d_in[3];
    float* out = (float*)d_out;

    cudaFuncSetAttribute(proj_kernel, cudaFuncAttributeMaxDynamicSharedMemorySize, P_SMEM);
    cudaFuncSetAttribute(attn_kernel, cudaFuncAttributeMaxDynamicSharedMemorySize, A_SMEM);

    split_kernel<<<(N4X + 2 * N4W) / 256, 256>>>(x, Wk, Wv);
    proj_kernel<<<dim3(128, 2), 256, P_SMEM>>>();
    attn_kernel<<<dim3(16, BN), 256, A_SMEM>>>(out);
}